// round 14
// baseline (speedup 1.0000x reference)
#include <cuda_runtime.h>
#include <cuda_fp16.h>
#include <cstdint>

// ---------------------------------------------------------------------------
// MultimodalRegionAwareAttention — fp16 mma.sync, round 14
//   Round-12 design re-gridded for occupancy: CTA = (b,h,n,qm), 128 threads,
//   4 warps (warp-M=16, M=64/CTA), launch_bounds(128,5) -> 5 CTAs/SM
//   (20 warps vs 16), finer 4-warp barriers, 5 independent barrier domains.
//   l kept as per-lane partials, one quad-reduce at task end.
// ---------------------------------------------------------------------------

#define BQ 2
#define NH 4
#define MBH_STRIDE 262144              // 64 regions * 64 * 64 (elements)
#define QSC 0.18033688011112042f       // (1/sqrt(64)) * log2(e)

__device__ __half g_qh[4*2*4*64*64*64];
__device__ __half g_kh[4*2*4*64*64*64];
__device__ __half g_vh[4*2*4*64*64*64];

__device__ __forceinline__ uint32_t smaddr(const void* p) {
    return (uint32_t)__cvta_generic_to_shared(p);
}
__device__ __forceinline__ float ex2(float x) {
    float y; asm("ex2.approx.f32 %0, %1;" : "=f"(y) : "f"(x));
    return y;
}
__device__ __forceinline__ uint32_t packh2(float lo, float hi) {
    uint32_t r;
    asm("cvt.rn.f16x2.f32 %0, %1, %2;" : "=r"(r) : "f"(hi), "f"(lo));
    return r;
}

#define CP16(dst, src) \
    asm volatile("cp.async.cg.shared.global [%0], [%1], 16;" :: "r"(dst), "l"(src))

__device__ __forceinline__ void ldsm4(uint32_t& r0, uint32_t& r1,
                                      uint32_t& r2, uint32_t& r3, uint32_t a) {
    asm volatile("ldmatrix.sync.aligned.m8n8.x4.shared.b16 {%0,%1,%2,%3}, [%4];"
                 : "=r"(r0), "=r"(r1), "=r"(r2), "=r"(r3) : "r"(a));
}

#define MMA_FP16(c, a, b0, b1)                                                 \
    asm volatile(                                                              \
        "mma.sync.aligned.m16n8k16.row.col.f32.f16.f16.f32 "                   \
        "{%0,%1,%2,%3},{%4,%5,%6,%7},{%8,%9},{%0,%1,%2,%3};"                   \
        : "+f"((c)[0]), "+f"((c)[1]), "+f"((c)[2]), "+f"((c)[3])               \
        : "r"((a)[0]), "r"((a)[1]), "r"((a)[2]), "r"((a)[3]),                  \
          "r"(b0), "r"(b1))

// ---------------------------------------------------------------------------
// Repack (unchanged). grid (256, 2, 12), 256 threads. fp16 out.
//   z 0..7:  q (scaled) / k -> transposed [n][pos/key][hd]
//   z 8..11: v -> plain [n][hd][key]
// ---------------------------------------------------------------------------
struct Ptrs12 { const float4* p[12]; };

__global__ void repack_all(Ptrs12 ptrs) {
    const int z = blockIdx.z;
    const int tid = threadIdx.x;

    if (z >= 8) {                       // v: plain relayout [n][hd][key]
        const int mod = z - 8;
        const int c = blockIdx.x, b = blockIdx.y;
        const int h = c >> 6, r = c & 63;
        const float4* src = ptrs.p[8 + mod] + (size_t)(b * 256 + c) * 1024;
        __half* dst = g_vh + (size_t)((mod * BQ + b) * NH + h) * MBH_STRIDE + r * 64;
        #pragma unroll
        for (int it = 0; it < 4; it++) {
            int cid = tid + it * 256;
            float4 v = src[cid];
            int dblk = cid & 3, ww = (cid >> 2) & 15, hh = cid >> 6;
            int n = (hh >> 2) * 16 + (ww >> 2) * 4 + dblk;
            int posb = (hh & 3) * 16 + (ww & 3) * 4;
            uint2 o2;
            o2.x = packh2(v.x, v.y);
            o2.y = packh2(v.z, v.w);
            *(uint2*)(dst + n * 4096 + posb) = o2;
        }
    } else {                            // q/k: transpose -> [n][pos/key][hd]
        __shared__ float sm[64 * 65];
        const int mod = z & 3;
        const int n = blockIdx.x & 63, h = blockIdx.x >> 6, b = blockIdx.y;
        const float4* src = ptrs.p[z];
        const float scale = (z < 4) ? QSC : 1.0f;
        const int hblk = n >> 4, wblk = (n >> 2) & 3, dblk = n & 3;

        #pragma unroll
        for (int i = 0; i < 4; i++) {
            int c = tid + i * 256;
            int r = c >> 4, pq = c & 15;
            int pl = pq >> 2, ql = pq & 3;
            int sidx = (((b * 256 + h * 64 + r) * 4096) +
                        (hblk * 4 + pl) * 256 + (wblk * 4 + ql) * 16 + dblk * 4) >> 2;
            float4 v = src[sidx];
            int pos = pq * 4;
            sm[r * 65 + pos + 0] = v.x * scale;
            sm[r * 65 + pos + 1] = v.y * scale;
            sm[r * 65 + pos + 2] = v.z * scale;
            sm[r * 65 + pos + 3] = v.w * scale;
        }
        __syncthreads();

        __half* base = (z < 4) ? g_qh : g_kh;
        __half* dst = base + (size_t)((mod * BQ + b) * NH + h) * MBH_STRIDE + n * 4096;
        #pragma unroll
        for (int i = 0; i < 4; i++) {
            int c = tid + i * 256;
            int pos = c >> 4, r4 = (c & 15) * 4;
            uint2 o2;
            o2.x = packh2(sm[(r4 + 0) * 65 + pos], sm[(r4 + 1) * 65 + pos]);
            o2.y = packh2(sm[(r4 + 2) * 65 + pos], sm[(r4 + 3) * 65 + pos]);
            *(uint2*)(dst + pos * 64 + r4) = o2;
        }
    }
}

// ---------------------------------------------------------------------------
// Attention — 128 threads, CTA = (b,h,n) x qm
// ---------------------------------------------------------------------------
#define KVB 8192                        // one K or V tile, bytes (64x64 fp16)
#define SMEM_BYTES (4 * KVB)            // KB0 KB1 VB0 VB1 = 32KB

__global__ void __launch_bounds__(128, 5)
attn(const int* __restrict__ mask,
     const int* __restrict__ rg0, const int* __restrict__ rg1,
     const int* __restrict__ rg2, const int* __restrict__ rg3,
     float* __restrict__ out) {
    extern __shared__ char smc[];
    const uint32_t smb = smaddr(smc);
    __shared__ int s_off[16];
    __shared__ int s_T;

    const int bhn = blockIdx.x;                 // 0..511
    const int qm  = blockIdx.y;                 // q modality 0..3
    const int b = bhn >> 8, h = (bhn >> 6) & 3, n = bhn & 63;

    const int tid  = threadIdx.x;
    const int w    = tid >> 5;                  // 0..3
    const int lane = tid & 31;
    const int g    = lane >> 2;
    const int t4   = lane & 3;
    const int l7   = lane & 7;
    const int l3   = lane >> 3;

    if (tid == 0) {
        const int* rgs[4] = { rg0, rg1, rg2, rg3 };
        int T = 0;
        const int rbase = ((b * NH + h) * 64 + n) * 4;
        for (int m = 0; m < 4; m++) {
            if (mask[b * 4 + m] != 0) {
                int mb = ((m * BQ + b) * NH + h) * MBH_STRIDE;
                for (int tk = 0; tk < 4; tk++)
                    s_off[T++] = mb + rgs[m][rbase + tk] * 4096;
            }
        }
        s_T = T;
    }

    // ---- Q A-fragments (fp16x2) in registers for the whole task ----
    const int pos = w * 16 + g;                // M row (0..55), rows pos/pos+8
    const uint32_t* q32 = (const uint32_t*)(g_qh
        + (size_t)((qm * BQ + b) * NH + h) * MBH_STRIDE
        + (size_t)n * 4096);
    uint32_t qa[4][4];
    #pragma unroll
    for (int kk = 0; kk < 4; kk++) {
        qa[kk][0] = q32[pos * 32 + kk * 8 + t4];
        qa[kk][1] = q32[(pos + 8) * 32 + kk * 8 + t4];
        qa[kk][2] = q32[pos * 32 + kk * 8 + 4 + t4];
        qa[kk][3] = q32[(pos + 8) * 32 + kk * 8 + 4 + t4];
    }

    __syncthreads();                 // s_off/s_T visible
    const int T = s_T;

    // smem swizzle: granule (row, j) -> row*128 + ((j ^ (row&7))*16)
    auto prefetch = [&](int t) {
        const char* ks = (const char*)(g_kh + s_off[t]);
        const char* vs = (const char*)(g_vh + s_off[t]);
        uint32_t kd = smb + (t & 1) * KVB;
        uint32_t vd = smb + 2 * KVB + (t & 1) * KVB;
        #pragma unroll
        for (int i = 0; i < 4; i++) {
            int c = tid + i * 128;               // 0..511 granules
            int row = c >> 3, j = c & 7;
            uint32_t so = (uint32_t)(row * 128 + ((j ^ (row & 7)) << 4));
            CP16(kd + so, ks + c * 16);
            CP16(vd + so, vs + c * 16);
        }
    };

    if (T > 0) prefetch(0);
    asm volatile("cp.async.commit_group;" ::: "memory");

    float cS[8][4];
    float o[8][4];
    #pragma unroll
    for (int nn = 0; nn < 8; nn++)
        #pragma unroll
        for (int j = 0; j < 4; j++) o[nn][j] = 0.0f;
    float l0 = 0.0f, l1 = 0.0f;                 // per-lane partials

    // per-lane ldmatrix base offsets (within a tile buffer)
    const uint32_t lm_lo = (uint32_t)(l7 * 128 + ((l3 ^ l7) << 4));
    const uint32_t lm_hi = (uint32_t)(l7 * 128 + (((4 + l3) ^ l7) << 4));

    for (int t = 0; t < T; t++) {
        if (t > 0) __syncthreads();              // WAR on buf (t+1)&1

        if (t + 1 < T) prefetch(t + 1);
        asm volatile("cp.async.commit_group;" ::: "memory");
        asm volatile("cp.async.wait_group 1;" ::: "memory");
        __syncthreads();                         // buf t&1 visible

        const uint32_t kb = smb + (t & 1) * KVB;
        const uint32_t vb = smb + 2 * KVB + (t & 1) * KVB;

        // ---- S = Q @ K^T : tile c = keys 8c..8c+7 ----
        #pragma unroll
        for (int c = 0; c < 8; c++) {
            #pragma unroll
            for (int j = 0; j < 4; j++) cS[c][j] = 0.0f;
            uint32_t b0, b1, b2, b3, b4, b5, b6, b7;
            ldsm4(b0, b1, b2, b3, kb + lm_lo + c * 1024);
            ldsm4(b4, b5, b6, b7, kb + lm_hi + c * 1024);
            MMA_FP16(cS[c], qa[0], b0, b1);
            MMA_FP16(cS[c], qa[1], b2, b3);
            MMA_FP16(cS[c], qa[2], b4, b5);
            MMA_FP16(cS[c], qa[3], b6, b7);
        }

        // ---- no-max softmax: P = exp2(S); per-lane partial row sums ----
        #pragma unroll
        for (int c = 0; c < 8; c++) {
            cS[c][0] = ex2(cS[c][0]);
            cS[c][1] = ex2(cS[c][1]);
            cS[c][2] = ex2(cS[c][2]);
            cS[c][3] = ex2(cS[c][3]);
            l0 += cS[c][0] + cS[c][1];
            l1 += cS[c][2] + cS[c][3];
        }

        // ---- P A-fragments: accumulator layout == fp16 A layout ----
        uint32_t pa[4][4];
        #pragma unroll
        for (int kk = 0; kk < 4; kk++) {
            pa[kk][0] = packh2(cS[2*kk][0],   cS[2*kk][1]);
            pa[kk][1] = packh2(cS[2*kk][2],   cS[2*kk][3]);
            pa[kk][2] = packh2(cS[2*kk+1][0], cS[2*kk+1][1]);
            pa[kk][3] = packh2(cS[2*kk+1][2], cS[2*kk+1][3]);
        }

        // ---- O += P @ V : tile nn = hd 8nn..8nn+7 ----
        #pragma unroll
        for (int nn = 0; nn < 8; nn++) {
            uint32_t b0, b1, b2, b3, b4, b5, b6, b7;
            ldsm4(b0, b1, b2, b3, vb + lm_lo + nn * 1024);
            ldsm4(b4, b5, b6, b7, vb + lm_hi + nn * 1024);
            MMA_FP16(o[nn], pa[0], b0, b1);
            MMA_FP16(o[nn], pa[1], b2, b3);
            MMA_FP16(o[nn], pa[2], b4, b5);
            MMA_FP16(o[nn], pa[3], b6, b7);
        }
    }

    // ---- finalize l (one quad-reduce for the whole task) ----
    l0 += __shfl_xor_sync(0xffffffffu, l0, 1);
    l0 += __shfl_xor_sync(0xffffffffu, l0, 2);
    l1 += __shfl_xor_sync(0xffffffffu, l1, 1);
    l1 += __shfl_xor_sync(0xffffffffu, l1, 2);

    // ---- epilogue: normalize + scatter ----
    const float i0 = 1.0f / l0, i1 = 1.0f / l1;
    const int pos0 = pos;
    const int pos1 = pos + 8;
    const int hblk = n >> 4, wblk = (n >> 2) & 3, dblk = n & 3;
    const int sp0 = (hblk * 4 + (pos0 >> 4)) * 256
                  + (wblk * 4 + ((pos0 >> 2) & 3)) * 16 + dblk * 4 + (pos0 & 3);
    const int sp1 = (hblk * 4 + (pos1 >> 4)) * 256
                  + (wblk * 4 + ((pos1 >> 2) & 3)) * 16 + dblk * 4 + (pos1 & 3);
    const size_t obase = (size_t)((qm * BQ + b) * 256 + h * 64) * 4096;

    #pragma unroll
    for (int nn = 0; nn < 8; nn++) {
        const int hd0 = 8 * nn + 2 * t4;
        out[obase + (size_t)hd0 * 4096 + sp0]       = o[nn][0] * i0;
        out[obase + (size_t)(hd0 + 1) * 4096 + sp0] = o[nn][1] * i0;
        out[obase + (size_t)hd0 * 4096 + sp1]       = o[nn][2] * i1;
        out[obase + (size_t)(hd0 + 1) * 4096 + sp1] = o[nn][3] * i1;
    }
}

// ---------------------------------------------------------------------------
// Launch
// ---------------------------------------------------------------------------
extern "C" void kernel_launch(void* const* d_in, const int* in_sizes, int n_in,
                              void* d_out, int out_size) {
    (void)in_sizes; (void)n_in; (void)out_size;

    // d_in: mask, q0..q3, k0..k3, v0..v3, rg0..rg3
    Ptrs12 ptrs;
    for (int i = 0; i < 12; i++) ptrs.p[i] = (const float4*)d_in[1 + i];

    dim3 rgrid(256, BQ, 12);
    repack_all<<<rgrid, 256>>>(ptrs);

    cudaFuncSetAttribute(attn, cudaFuncAttributeMaxDynamicSharedMemorySize,
                         SMEM_BYTES);
    dim3 agrid(BQ * NH * 64, 4);          // (512, 4): CTA per (b,h,n,qm)
    attn<<<agrid, 128, SMEM_BYTES>>>(
        (const int*)d_in[0],
        (const int*)d_in[13], (const int*)d_in[14],
        (const int*)d_in[15], (const int*)d_in[16],
        (float*)d_out);
}

// round 15
// speedup vs baseline: 1.0291x; 1.0291x over previous
#include <cuda_runtime.h>
#include <cuda_fp16.h>
#include <cstdint>

// ---------------------------------------------------------------------------
// MultimodalRegionAwareAttention — fp16 mma.sync, round 15
//   Round-12 base (256 thr, CTA=(b,h,n)x qm-pair, warp-M=16) with:
//   - 3-stage K/V smem ring, prefetch depth 2
//   - ONE __syncthreads per tile (wait_group is positional; always-commit)
//   - l as per-lane partials, single quad-reduce at task end
// ---------------------------------------------------------------------------

#define BQ 2
#define NH 4
#define MBH_STRIDE 262144              // 64 regions * 64 * 64 (elements)
#define QSC 0.18033688011112042f       // (1/sqrt(64)) * log2(e)

__device__ __half g_qh[4*2*4*64*64*64];
__device__ __half g_kh[4*2*4*64*64*64];
__device__ __half g_vh[4*2*4*64*64*64];

__device__ __forceinline__ uint32_t smaddr(const void* p) {
    return (uint32_t)__cvta_generic_to_shared(p);
}
__device__ __forceinline__ float ex2(float x) {
    float y; asm("ex2.approx.f32 %0, %1;" : "=f"(y) : "f"(x));
    return y;
}
__device__ __forceinline__ uint32_t packh2(float lo, float hi) {
    uint32_t r;
    asm("cvt.rn.f16x2.f32 %0, %1, %2;" : "=r"(r) : "f"(hi), "f"(lo));
    return r;
}

#define CP16(dst, src) \
    asm volatile("cp.async.cg.shared.global [%0], [%1], 16;" :: "r"(dst), "l"(src))

__device__ __forceinline__ void ldsm4(uint32_t& r0, uint32_t& r1,
                                      uint32_t& r2, uint32_t& r3, uint32_t a) {
    asm volatile("ldmatrix.sync.aligned.m8n8.x4.shared.b16 {%0,%1,%2,%3}, [%4];"
                 : "=r"(r0), "=r"(r1), "=r"(r2), "=r"(r3) : "r"(a));
}

#define MMA_FP16(c, a, b0, b1)                                                 \
    asm volatile(                                                              \
        "mma.sync.aligned.m16n8k16.row.col.f32.f16.f16.f32 "                   \
        "{%0,%1,%2,%3},{%4,%5,%6,%7},{%8,%9},{%0,%1,%2,%3};"                   \
        : "+f"((c)[0]), "+f"((c)[1]), "+f"((c)[2]), "+f"((c)[3])               \
        : "r"((a)[0]), "r"((a)[1]), "r"((a)[2]), "r"((a)[3]),                  \
          "r"(b0), "r"(b1))

// ---------------------------------------------------------------------------
// Repack (unchanged). grid (256, 2, 12), 256 threads. fp16 out.
//   z 0..7:  q (scaled) / k -> transposed [n][pos/key][hd]
//   z 8..11: v -> plain [n][hd][key]
// ---------------------------------------------------------------------------
struct Ptrs12 { const float4* p[12]; };

__global__ void repack_all(Ptrs12 ptrs) {
    const int z = blockIdx.z;
    const int tid = threadIdx.x;

    if (z >= 8) {                       // v: plain relayout [n][hd][key]
        const int mod = z - 8;
        const int c = blockIdx.x, b = blockIdx.y;
        const int h = c >> 6, r = c & 63;
        const float4* src = ptrs.p[8 + mod] + (size_t)(b * 256 + c) * 1024;
        __half* dst = g_vh + (size_t)((mod * BQ + b) * NH + h) * MBH_STRIDE + r * 64;
        #pragma unroll
        for (int it = 0; it < 4; it++) {
            int cid = tid + it * 256;
            float4 v = src[cid];
            int dblk = cid & 3, ww = (cid >> 2) & 15, hh = cid >> 6;
            int n = (hh >> 2) * 16 + (ww >> 2) * 4 + dblk;
            int posb = (hh & 3) * 16 + (ww & 3) * 4;
            uint2 o2;
            o2.x = packh2(v.x, v.y);
            o2.y = packh2(v.z, v.w);
            *(uint2*)(dst + n * 4096 + posb) = o2;
        }
    } else {                            // q/k: transpose -> [n][pos/key][hd]
        __shared__ float sm[64 * 65];
        const int mod = z & 3;
        const int n = blockIdx.x & 63, h = blockIdx.x >> 6, b = blockIdx.y;
        const float4* src = ptrs.p[z];
        const float scale = (z < 4) ? QSC : 1.0f;
        const int hblk = n >> 4, wblk = (n >> 2) & 3, dblk = n & 3;

        #pragma unroll
        for (int i = 0; i < 4; i++) {
            int c = tid + i * 256;
            int r = c >> 4, pq = c & 15;
            int pl = pq >> 2, ql = pq & 3;
            int sidx = (((b * 256 + h * 64 + r) * 4096) +
                        (hblk * 4 + pl) * 256 + (wblk * 4 + ql) * 16 + dblk * 4) >> 2;
            float4 v = src[sidx];
            int pos = pq * 4;
            sm[r * 65 + pos + 0] = v.x * scale;
            sm[r * 65 + pos + 1] = v.y * scale;
            sm[r * 65 + pos + 2] = v.z * scale;
            sm[r * 65 + pos + 3] = v.w * scale;
        }
        __syncthreads();

        __half* base = (z < 4) ? g_qh : g_kh;
        __half* dst = base + (size_t)((mod * BQ + b) * NH + h) * MBH_STRIDE + n * 4096;
        #pragma unroll
        for (int i = 0; i < 4; i++) {
            int c = tid + i * 256;
            int pos = c >> 4, r4 = (c & 15) * 4;
            uint2 o2;
            o2.x = packh2(sm[(r4 + 0) * 65 + pos], sm[(r4 + 1) * 65 + pos]);
            o2.y = packh2(sm[(r4 + 2) * 65 + pos], sm[(r4 + 3) * 65 + pos]);
            *(uint2*)(dst + pos * 64 + r4) = o2;
        }
    }
}

// ---------------------------------------------------------------------------
// Attention — 256 threads, 3-stage ring, one barrier per tile
// ---------------------------------------------------------------------------
#define STGB 16384                      // one stage: K(8KB) + V(8KB)
#define SMEM_BYTES (3 * STGB)           // 48KB

__global__ void __launch_bounds__(256, 2)
attn(const int* __restrict__ mask,
     const int* __restrict__ rg0, const int* __restrict__ rg1,
     const int* __restrict__ rg2, const int* __restrict__ rg3,
     float* __restrict__ out) {
    extern __shared__ char smc[];
    const uint32_t smb = smaddr(smc);
    __shared__ int s_off[16];
    __shared__ int s_T;

    const int bhn = blockIdx.x;                 // 0..511
    const int qp  = blockIdx.y;                 // q-mod pair 0..1
    const int b = bhn >> 8, h = (bhn >> 6) & 3, n = bhn & 63;

    const int tid  = threadIdx.x;
    const int w    = tid >> 5;
    const int lane = tid & 31;
    const int g    = lane >> 2;
    const int t4   = lane & 3;
    const int l7   = lane & 7;
    const int l3   = lane >> 3;

    if (tid == 0) {
        const int* rgs[4] = { rg0, rg1, rg2, rg3 };
        int T = 0;
        const int rbase = ((b * NH + h) * 64 + n) * 4;
        for (int m = 0; m < 4; m++) {
            if (mask[b * 4 + m] != 0) {
                int mb = ((m * BQ + b) * NH + h) * MBH_STRIDE;
                for (int tk = 0; tk < 4; tk++)
                    s_off[T++] = mb + rgs[m][rbase + tk] * 4096;
            }
        }
        s_T = T;
    }

    // ---- Q A-fragments (fp16x2) in registers for the whole task ----
    const int qrow = w * 16 + g;
    const int qm   = qrow >> 6;
    const int pos  = qrow & 63;
    const uint32_t* q32 = (const uint32_t*)(g_qh
        + (size_t)((qp * 2 + qm) * BQ + b) * NH * MBH_STRIDE
        + (size_t)h * MBH_STRIDE + (size_t)n * 4096);
    uint32_t qa[4][4];
    #pragma unroll
    for (int kk = 0; kk < 4; kk++) {
        qa[kk][0] = q32[pos * 32 + kk * 8 + t4];
        qa[kk][1] = q32[(pos + 8) * 32 + kk * 8 + t4];
        qa[kk][2] = q32[pos * 32 + kk * 8 + 4 + t4];
        qa[kk][3] = q32[(pos + 8) * 32 + kk * 8 + 4 + t4];
    }

    __syncthreads();                 // s_off/s_T visible
    const int T = s_T;

    // smem swizzle: granule (row, j) -> row*128 + ((j ^ (row&7))*16)
    auto prefetch = [&](int t) {
        const char* ks = (const char*)(g_kh + s_off[t]);
        const char* vs = (const char*)(g_vh + s_off[t]);
        const uint32_t st = smb + (uint32_t)(t % 3) * STGB;
        #pragma unroll
        for (int i = 0; i < 2; i++) {
            int c = tid + i * 256;               // 0..511 granules
            int row = c >> 3, j = c & 7;
            uint32_t so = (uint32_t)(row * 128 + ((j ^ (row & 7)) << 4));
            CP16(st + so, ks + c * 16);
            CP16(st + 8192 + so, vs + c * 16);
        }
    };

    // prefetch depth 2; commits are ALWAYS issued to keep wait_group positional
    if (T > 0) prefetch(0);
    asm volatile("cp.async.commit_group;" ::: "memory");
    if (T > 1) prefetch(1);
    asm volatile("cp.async.commit_group;" ::: "memory");

    float cS[8][4];
    float o[8][4];
    #pragma unroll
    for (int nn = 0; nn < 8; nn++)
        #pragma unroll
        for (int j = 0; j < 4; j++) o[nn][j] = 0.0f;
    float l0 = 0.0f, l1 = 0.0f;                 // per-lane partials

    const uint32_t lm_lo = (uint32_t)(l7 * 128 + ((l3 ^ l7) << 4));
    const uint32_t lm_hi = (uint32_t)(l7 * 128 + (((4 + l3) ^ l7) << 4));

    for (int t = 0; t < T; t++) {
        // all but the newest commit-group complete => tile-t data arrived
        asm volatile("cp.async.wait_group 1;" ::: "memory");
        // one barrier: (a) tile-t data visible to all warps (everyone waited),
        // (b) all warps finished compute(t-1) => stage (t+2)%3 == (t-1)%3 free
        __syncthreads();

        if (t + 2 < T) prefetch(t + 2);
        asm volatile("cp.async.commit_group;" ::: "memory");   // always

        const uint32_t kb = smb + (uint32_t)(t % 3) * STGB;
        const uint32_t vb = kb + 8192;

        // ---- S = Q @ K^T : tile c = keys 8c..8c+7 ----
        #pragma unroll
        for (int c = 0; c < 8; c++) {
            #pragma unroll
            for (int j = 0; j < 4; j++) cS[c][j] = 0.0f;
            uint32_t b0, b1, b2, b3, b4, b5, b6, b7;
            ldsm4(b0, b1, b2, b3, kb + lm_lo + c * 1024);
            ldsm4(b4, b5, b6, b7, kb + lm_hi + c * 1024);
            MMA_FP16(cS[c], qa[0], b0, b1);
            MMA_FP16(cS[c], qa[1], b2, b3);
            MMA_FP16(cS[c], qa[2], b4, b5);
            MMA_FP16(cS[c], qa[3], b6, b7);
        }

        // ---- no-max softmax: P = exp2(S); per-lane partial row sums ----
        #pragma unroll
        for (int c = 0; c < 8; c++) {
            cS[c][0] = ex2(cS[c][0]);
            cS[c][1] = ex2(cS[c][1]);
            cS[c][2] = ex2(cS[c][2]);
            cS[c][3] = ex2(cS[c][3]);
            l0 += cS[c][0] + cS[c][1];
            l1 += cS[c][2] + cS[c][3];
        }

        // ---- P A-fragments: accumulator layout == fp16 A layout ----
        uint32_t pa[4][4];
        #pragma unroll
        for (int kk = 0; kk < 4; kk++) {
            pa[kk][0] = packh2(cS[2*kk][0],   cS[2*kk][1]);
            pa[kk][1] = packh2(cS[2*kk][2],   cS[2*kk][3]);
            pa[kk][2] = packh2(cS[2*kk+1][0], cS[2*kk+1][1]);
            pa[kk][3] = packh2(cS[2*kk+1][2], cS[2*kk+1][3]);
        }

        // ---- O += P @ V : tile nn = hd 8nn..8nn+7 ----
        #pragma unroll
        for (int nn = 0; nn < 8; nn++) {
            uint32_t b0, b1, b2, b3, b4, b5, b6, b7;
            ldsm4(b0, b1, b2, b3, vb + lm_lo + nn * 1024);
            ldsm4(b4, b5, b6, b7, vb + lm_hi + nn * 1024);
            MMA_FP16(o[nn], pa[0], b0, b1);
            MMA_FP16(o[nn], pa[1], b2, b3);
            MMA_FP16(o[nn], pa[2], b4, b5);
            MMA_FP16(o[nn], pa[3], b6, b7);
        }
    }

    // ---- finalize l (one quad-reduce for the whole task) ----
    l0 += __shfl_xor_sync(0xffffffffu, l0, 1);
    l0 += __shfl_xor_sync(0xffffffffu, l0, 2);
    l1 += __shfl_xor_sync(0xffffffffu, l1, 1);
    l1 += __shfl_xor_sync(0xffffffffu, l1, 2);

    // ---- epilogue: normalize + scatter ----
    const float i0 = 1.0f / l0, i1 = 1.0f / l1;
    const int pos0 = pos;
    const int pos1 = pos + 8;
    const int hblk = n >> 4, wblk = (n >> 2) & 3, dblk = n & 3;
    const int sp0 = (hblk * 4 + (pos0 >> 4)) * 256
                  + (wblk * 4 + ((pos0 >> 2) & 3)) * 16 + dblk * 4 + (pos0 & 3);
    const int sp1 = (hblk * 4 + (pos1 >> 4)) * 256
                  + (wblk * 4 + ((pos1 >> 2) & 3)) * 16 + dblk * 4 + (pos1 & 3);
    const size_t obase = (size_t)(((qp * 2 + qm) * BQ + b) * 256 + h * 64) * 4096;

    #pragma unroll
    for (int nn = 0; nn < 8; nn++) {
        const int hd0 = 8 * nn + 2 * t4;
        out[obase + (size_t)hd0 * 4096 + sp0]       = o[nn][0] * i0;
        out[obase + (size_t)(hd0 + 1) * 4096 + sp0] = o[nn][1] * i0;
        out[obase + (size_t)hd0 * 4096 + sp1]       = o[nn][2] * i1;
        out[obase + (size_t)(hd0 + 1) * 4096 + sp1] = o[nn][3] * i1;
    }
}

// ---------------------------------------------------------------------------
// Launch
// ---------------------------------------------------------------------------
extern "C" void kernel_launch(void* const* d_in, const int* in_sizes, int n_in,
                              void* d_out, int out_size) {
    (void)in_sizes; (void)n_in; (void)out_size;

    // d_in: mask, q0..q3, k0..k3, v0..v3, rg0..rg3
    Ptrs12 ptrs;
    for (int i = 0; i < 12; i++) ptrs.p[i] = (const float4*)d_in[1 + i];

    dim3 rgrid(256, BQ, 12);
    repack_all<<<rgrid, 256>>>(ptrs);

    cudaFuncSetAttribute(attn, cudaFuncAttributeMaxDynamicSharedMemorySize,
                         SMEM_BYTES);
    dim3 agrid(BQ * NH * 64, 2);          // (512, 2)
    attn<<<agrid, 256, SMEM_BYTES>>>(
        (const int*)d_in[0],
        (const int*)d_in[13], (const int*)d_in[14],
        (const int*)d_in[15], (const int*)d_in[16],
        (float*)d_out);
}

// round 16
// speedup vs baseline: 1.1442x; 1.1119x over previous
#include <cuda_runtime.h>
#include <cuda_fp16.h>
#include <cstdint>

// ---------------------------------------------------------------------------
// MultimodalRegionAwareAttention — fp16 mma.sync, round 16
//   Software-pipelined: S(t) interleaved with PV(t-1) (64 independent HMMAs
//   per compute block). 4-stage K/V ring, one barrier per tile, always-commit.
//   l per-lane partials, single end-of-task quad-reduce.
// ---------------------------------------------------------------------------

#define BQ 2
#define NH 4
#define MBH_STRIDE 262144              // 64 regions * 64 * 64 (elements)
#define QSC 0.18033688011112042f       // (1/sqrt(64)) * log2(e)

__device__ __half g_qh[4*2*4*64*64*64];
__device__ __half g_kh[4*2*4*64*64*64];
__device__ __half g_vh[4*2*4*64*64*64];

__device__ __forceinline__ uint32_t smaddr(const void* p) {
    return (uint32_t)__cvta_generic_to_shared(p);
}
__device__ __forceinline__ float ex2(float x) {
    float y; asm("ex2.approx.f32 %0, %1;" : "=f"(y) : "f"(x));
    return y;
}
__device__ __forceinline__ uint32_t packh2(float lo, float hi) {
    uint32_t r;
    asm("cvt.rn.f16x2.f32 %0, %1, %2;" : "=r"(r) : "f"(hi), "f"(lo));
    return r;
}

#define CP16(dst, src) \
    asm volatile("cp.async.cg.shared.global [%0], [%1], 16;" :: "r"(dst), "l"(src))

__device__ __forceinline__ void ldsm4(uint32_t& r0, uint32_t& r1,
                                      uint32_t& r2, uint32_t& r3, uint32_t a) {
    asm volatile("ldmatrix.sync.aligned.m8n8.x4.shared.b16 {%0,%1,%2,%3}, [%4];"
                 : "=r"(r0), "=r"(r1), "=r"(r2), "=r"(r3) : "r"(a));
}

#define MMA_FP16(c, a, b0, b1)                                                 \
    asm volatile(                                                              \
        "mma.sync.aligned.m16n8k16.row.col.f32.f16.f16.f32 "                   \
        "{%0,%1,%2,%3},{%4,%5,%6,%7},{%8,%9},{%0,%1,%2,%3};"                   \
        : "+f"((c)[0]), "+f"((c)[1]), "+f"((c)[2]), "+f"((c)[3])               \
        : "r"((a)[0]), "r"((a)[1]), "r"((a)[2]), "r"((a)[3]),                  \
          "r"(b0), "r"(b1))

// ---------------------------------------------------------------------------
// Repack (unchanged). grid (256, 2, 12), 256 threads. fp16 out.
// ---------------------------------------------------------------------------
struct Ptrs12 { const float4* p[12]; };

__global__ void repack_all(Ptrs12 ptrs) {
    const int z = blockIdx.z;
    const int tid = threadIdx.x;

    if (z >= 8) {                       // v: plain relayout [n][hd][key]
        const int mod = z - 8;
        const int c = blockIdx.x, b = blockIdx.y;
        const int h = c >> 6, r = c & 63;
        const float4* src = ptrs.p[8 + mod] + (size_t)(b * 256 + c) * 1024;
        __half* dst = g_vh + (size_t)((mod * BQ + b) * NH + h) * MBH_STRIDE + r * 64;
        #pragma unroll
        for (int it = 0; it < 4; it++) {
            int cid = tid + it * 256;
            float4 v = src[cid];
            int dblk = cid & 3, ww = (cid >> 2) & 15, hh = cid >> 6;
            int n = (hh >> 2) * 16 + (ww >> 2) * 4 + dblk;
            int posb = (hh & 3) * 16 + (ww & 3) * 4;
            uint2 o2;
            o2.x = packh2(v.x, v.y);
            o2.y = packh2(v.z, v.w);
            *(uint2*)(dst + n * 4096 + posb) = o2;
        }
    } else {                            // q/k: transpose -> [n][pos/key][hd]
        __shared__ float sm[64 * 65];
        const int mod = z & 3;
        const int n = blockIdx.x & 63, h = blockIdx.x >> 6, b = blockIdx.y;
        const float4* src = ptrs.p[z];
        const float scale = (z < 4) ? QSC : 1.0f;
        const int hblk = n >> 4, wblk = (n >> 2) & 3, dblk = n & 3;

        #pragma unroll
        for (int i = 0; i < 4; i++) {
            int c = tid + i * 256;
            int r = c >> 4, pq = c & 15;
            int pl = pq >> 2, ql = pq & 3;
            int sidx = (((b * 256 + h * 64 + r) * 4096) +
                        (hblk * 4 + pl) * 256 + (wblk * 4 + ql) * 16 + dblk * 4) >> 2;
            float4 v = src[sidx];
            int pos = pq * 4;
            sm[r * 65 + pos + 0] = v.x * scale;
            sm[r * 65 + pos + 1] = v.y * scale;
            sm[r * 65 + pos + 2] = v.z * scale;
            sm[r * 65 + pos + 3] = v.w * scale;
        }
        __syncthreads();

        __half* base = (z < 4) ? g_qh : g_kh;
        __half* dst = base + (size_t)((mod * BQ + b) * NH + h) * MBH_STRIDE + n * 4096;
        #pragma unroll
        for (int i = 0; i < 4; i++) {
            int c = tid + i * 256;
            int pos = c >> 4, r4 = (c & 15) * 4;
            uint2 o2;
            o2.x = packh2(sm[(r4 + 0) * 65 + pos], sm[(r4 + 1) * 65 + pos]);
            o2.y = packh2(sm[(r4 + 2) * 65 + pos], sm[(r4 + 3) * 65 + pos]);
            *(uint2*)(dst + pos * 64 + r4) = o2;
        }
    }
}

// ---------------------------------------------------------------------------
// Attention — 256 threads, 4-stage ring, S(t) || PV(t-1)
// ---------------------------------------------------------------------------
#define STGB 16384                      // one stage: K(8KB) + V(8KB)
#define SMEM_BYTES (4 * STGB)           // 64KB

__global__ void __launch_bounds__(256, 2)
attn(const int* __restrict__ mask,
     const int* __restrict__ rg0, const int* __restrict__ rg1,
     const int* __restrict__ rg2, const int* __restrict__ rg3,
     float* __restrict__ out) {
    extern __shared__ char smc[];
    const uint32_t smb = smaddr(smc);
    __shared__ int s_off[16];
    __shared__ int s_T;

    const int bhn = blockIdx.x;                 // 0..511
    const int qp  = blockIdx.y;                 // q-mod pair 0..1
    const int b = bhn >> 8, h = (bhn >> 6) & 3, n = bhn & 63;

    const int tid  = threadIdx.x;
    const int w    = tid >> 5;
    const int lane = tid & 31;
    const int g    = lane >> 2;
    const int t4   = lane & 3;
    const int l7   = lane & 7;
    const int l3   = lane >> 3;

    if (tid == 0) {
        const int* rgs[4] = { rg0, rg1, rg2, rg3 };
        int T = 0;
        const int rbase = ((b * NH + h) * 64 + n) * 4;
        for (int m = 0; m < 4; m++) {
            if (mask[b * 4 + m] != 0) {
                int mb = ((m * BQ + b) * NH + h) * MBH_STRIDE;
                for (int tk = 0; tk < 4; tk++)
                    s_off[T++] = mb + rgs[m][rbase + tk] * 4096;
            }
        }
        s_T = T;
    }

    // ---- Q A-fragments (fp16x2) in registers for the whole task ----
    const int qrow = w * 16 + g;
    const int qm   = qrow >> 6;
    const int pos  = qrow & 63;
    const uint32_t* q32 = (const uint32_t*)(g_qh
        + (size_t)((qp * 2 + qm) * BQ + b) * NH * MBH_STRIDE
        + (size_t)h * MBH_STRIDE + (size_t)n * 4096);
    uint32_t qa[4][4];
    #pragma unroll
    for (int kk = 0; kk < 4; kk++) {
        qa[kk][0] = q32[pos * 32 + kk * 8 + t4];
        qa[kk][1] = q32[(pos + 8) * 32 + kk * 8 + t4];
        qa[kk][2] = q32[pos * 32 + kk * 8 + 4 + t4];
        qa[kk][3] = q32[(pos + 8) * 32 + kk * 8 + 4 + t4];
    }

    __syncthreads();                 // s_off/s_T visible
    const int T = s_T;

    // smem swizzle: granule (row, j) -> row*128 + ((j ^ (row&7))*16)
    auto prefetch = [&](int t) {
        const char* ks = (const char*)(g_kh + s_off[t]);
        const char* vs = (const char*)(g_vh + s_off[t]);
        const uint32_t st = smb + (uint32_t)(t & 3) * STGB;
        #pragma unroll
        for (int i = 0; i < 2; i++) {
            int c = tid + i * 256;               // 0..511 granules
            int row = c >> 3, j = c & 7;
            uint32_t so = (uint32_t)(row * 128 + ((j ^ (row & 7)) << 4));
            CP16(st + so, ks + c * 16);
            CP16(st + 8192 + so, vs + c * 16);
        }
    };

    float cS[8][4];
    float o[8][4];
    uint32_t pa[4][4];                           // loop-carried P fragments
    #pragma unroll
    for (int nn = 0; nn < 8; nn++)
        #pragma unroll
        for (int j = 0; j < 4; j++) o[nn][j] = 0.0f;
    float l0 = 0.0f, l1 = 0.0f;

    const uint32_t lm_lo = (uint32_t)(l7 * 128 + ((l3 ^ l7) << 4));
    const uint32_t lm_hi = (uint32_t)(l7 * 128 + (((4 + l3) ^ l7) << 4));

    // ---- S of one tile (no PV interleave) ----
    auto computeS = [&](uint32_t kb) {
        #pragma unroll
        for (int c = 0; c < 8; c++) {
            #pragma unroll
            for (int j = 0; j < 4; j++) cS[c][j] = 0.0f;
            uint32_t b0, b1, b2, b3, b4, b5, b6, b7;
            ldsm4(b0, b1, b2, b3, kb + lm_lo + c * 1024);
            ldsm4(b4, b5, b6, b7, kb + lm_hi + c * 1024);
            MMA_FP16(cS[c], qa[0], b0, b1);
            MMA_FP16(cS[c], qa[1], b2, b3);
            MMA_FP16(cS[c], qa[2], b4, b5);
            MMA_FP16(cS[c], qa[3], b6, b7);
        }
    };

    // ---- S(t) interleaved with PV(t-1): 64 independent HMMAs ----
    auto computeSPV = [&](uint32_t kb, uint32_t vb) {
        #pragma unroll
        for (int c = 0; c < 8; c++) {
            #pragma unroll
            for (int j = 0; j < 4; j++) cS[c][j] = 0.0f;
            uint32_t b0, b1, b2, b3, b4, b5, b6, b7;
            uint32_t v0, v1, v2, v3, v4, v5, v6, v7;
            ldsm4(b0, b1, b2, b3, kb + lm_lo + c * 1024);
            ldsm4(v0, v1, v2, v3, vb + lm_lo + c * 1024);
            MMA_FP16(cS[c], qa[0], b0, b1);
            MMA_FP16(o[c],  pa[0], v0, v1);
            MMA_FP16(cS[c], qa[1], b2, b3);
            MMA_FP16(o[c],  pa[1], v2, v3);
            ldsm4(b4, b5, b6, b7, kb + lm_hi + c * 1024);
            ldsm4(v4, v5, v6, v7, vb + lm_hi + c * 1024);
            MMA_FP16(cS[c], qa[2], b4, b5);
            MMA_FP16(o[c],  pa[2], v4, v5);
            MMA_FP16(cS[c], qa[3], b6, b7);
            MMA_FP16(o[c],  pa[3], v6, v7);
        }
    };

    // ---- PV only (tail) ----
    auto computePV = [&](uint32_t vb) {
        #pragma unroll
        for (int nn = 0; nn < 8; nn++) {
            uint32_t v0, v1, v2, v3, v4, v5, v6, v7;
            ldsm4(v0, v1, v2, v3, vb + lm_lo + nn * 1024);
            ldsm4(v4, v5, v6, v7, vb + lm_hi + nn * 1024);
            MMA_FP16(o[nn], pa[0], v0, v1);
            MMA_FP16(o[nn], pa[1], v2, v3);
            MMA_FP16(o[nn], pa[2], v4, v5);
            MMA_FP16(o[nn], pa[3], v6, v7);
        }
    };

    // ---- softmax: ex2, partial sums, pack into pa ----
    auto softmaxPack = [&]() {
        #pragma unroll
        for (int c = 0; c < 8; c++) {
            cS[c][0] = ex2(cS[c][0]);
            cS[c][1] = ex2(cS[c][1]);
            cS[c][2] = ex2(cS[c][2]);
            cS[c][3] = ex2(cS[c][3]);
            l0 += cS[c][0] + cS[c][1];
            l1 += cS[c][2] + cS[c][3];
        }
        #pragma unroll
        for (int kk = 0; kk < 4; kk++) {
            pa[kk][0] = packh2(cS[2*kk][0],   cS[2*kk][1]);
            pa[kk][1] = packh2(cS[2*kk][2],   cS[2*kk][3]);
            pa[kk][2] = packh2(cS[2*kk+1][0], cS[2*kk+1][1]);
            pa[kk][3] = packh2(cS[2*kk+1][2], cS[2*kk+1][3]);
        }
    };

    // ---- prologue: 3 commits (always), S(0), softmax(0) ----
    if (T > 0) prefetch(0);
    asm volatile("cp.async.commit_group;" ::: "memory");
    if (T > 1) prefetch(1);
    asm volatile("cp.async.commit_group;" ::: "memory");
    if (T > 2) prefetch(2);
    asm volatile("cp.async.commit_group;" ::: "memory");

    asm volatile("cp.async.wait_group 2;" ::: "memory");   // tile 0 done
    __syncthreads();

    if (T > 0) {
        computeS(smb);                    // stage 0
        softmaxPack();
    }

    // ---- main loop: S(t) || PV(t-1) ----
    for (int t = 1; t < T; t++) {
        // commits so far: tiles 0..t+1 ; all but newest done => tile t ready
        asm volatile("cp.async.wait_group 1;" ::: "memory");
        __syncthreads();   // visibility of tile t everywhere + all warps done iter t-1

        if (t + 2 < T) prefetch(t + 2);
        asm volatile("cp.async.commit_group;" ::: "memory");   // always

        const uint32_t kb = smb + (uint32_t)(t & 3) * STGB;
        const uint32_t vb = smb + (uint32_t)((t - 1) & 3) * STGB + 8192;
        computeSPV(kb, vb);
        softmaxPack();
    }

    // ---- tail: PV(T-1) ----
    if (T > 0)
        computePV(smb + (uint32_t)((T - 1) & 3) * STGB + 8192);

    // ---- finalize l ----
    l0 += __shfl_xor_sync(0xffffffffu, l0, 1);
    l0 += __shfl_xor_sync(0xffffffffu, l0, 2);
    l1 += __shfl_xor_sync(0xffffffffu, l1, 1);
    l1 += __shfl_xor_sync(0xffffffffu, l1, 2);

    // ---- epilogue: normalize + scatter ----
    const float i0 = 1.0f / l0, i1 = 1.0f / l1;
    const int pos0 = pos;
    const int pos1 = pos + 8;
    const int hblk = n >> 4, wblk = (n >> 2) & 3, dblk = n & 3;
    const int sp0 = (hblk * 4 + (pos0 >> 4)) * 256
                  + (wblk * 4 + ((pos0 >> 2) & 3)) * 16 + dblk * 4 + (pos0 & 3);
    const int sp1 = (hblk * 4 + (pos1 >> 4)) * 256
                  + (wblk * 4 + ((pos1 >> 2) & 3)) * 16 + dblk * 4 + (pos1 & 3);
    const size_t obase = (size_t)(((qp * 2 + qm) * BQ + b) * 256 + h * 64) * 4096;

    #pragma unroll
    for (int nn = 0; nn < 8; nn++) {
        const int hd0 = 8 * nn + 2 * t4;
        out[obase + (size_t)hd0 * 4096 + sp0]       = o[nn][0] * i0;
        out[obase + (size_t)(hd0 + 1) * 4096 + sp0] = o[nn][1] * i0;
        out[obase + (size_t)hd0 * 4096 + sp1]       = o[nn][2] * i1;
        out[obase + (size_t)(hd0 + 1) * 4096 + sp1] = o[nn][3] * i1;
    }
}

// ---------------------------------------------------------------------------
// Launch
// ---------------------------------------------------------------------------
extern "C" void kernel_launch(void* const* d_in, const int* in_sizes, int n_in,
                              void* d_out, int out_size) {
    (void)in_sizes; (void)n_in; (void)out_size;

    // d_in: mask, q0..q3, k0..k3, v0..v3, rg0..rg3
    Ptrs12 ptrs;
    for (int i = 0; i < 12; i++) ptrs.p[i] = (const float4*)d_in[1 + i];

    dim3 rgrid(256, BQ, 12);
    repack_all<<<rgrid, 256>>>(ptrs);

    cudaFuncSetAttribute(attn, cudaFuncAttributeMaxDynamicSharedMemorySize,
                         SMEM_BYTES);
    dim3 agrid(BQ * NH * 64, 2);          // (512, 2)
    attn<<<agrid, 256, SMEM_BYTES>>>(
        (const int*)d_in[0],
        (const int*)d_in[13], (const int*)d_in[14],
        (const int*)d_in[15], (const int*)d_in[16],
        (float*)d_out);
}